// round 3
// baseline (speedup 1.0000x reference)
#include <cuda_runtime.h>
#include <cuda_bf16.h>

// Problem constants (fixed by the dataset)
#define NNODES   100000
#define FIN      512
#define FHID     128
#define FOUT     40
#define NEDGES   3200000

// Scratch (device globals; no runtime allocation allowed)
__device__ __align__(256) float g_support1[(size_t)NNODES * FHID];  // X @ W1
__device__ __align__(256) float g_agg1[(size_t)NNODES * FHID];      // aggregated layer 1
__device__ __align__(256) float g_support2[(size_t)NNODES * FOUT];  // relu(agg1+b1) @ W2
__device__ __align__(256) int   g_src[NEDGES];
__device__ __align__(256) int   g_dst[NEDGES];
__device__ __align__(256) int   g_deg[NNODES];
__device__ __align__(256) int   g_off[NNODES + 1];
__device__ __align__(256) int   g_cursor[NNODES];
__device__ __align__(256) int   g_csr_src[NEDGES];
__device__ __align__(256) float g_csr_w[NEDGES];
__device__ int g_is64;

// ---------------------------------------------------------------------------
// Edge-index dtype detection (int64 vs int32 materialization)
// ---------------------------------------------------------------------------
__global__ void detect_kernel(const void* ei, int E, int M) {
    const long long* p64 = (const long long*)ei;
    int ok64 = 1;
    for (int i = 0; i < 4096; i++) {
        long long idx = (long long)i * (E / 4096);
        long long v = p64[idx];
        if (v < 0 || v >= M) { ok64 = 0; break; }
    }
    g_is64 = ok64;
}

__global__ void zero_deg_kernel(int M) {
    int i = blockIdx.x * blockDim.x + threadIdx.x;
    if (i < M) g_deg[i] = 0;
}

// decode edge ids to int32 + histogram of dst degrees
__global__ void decode_hist_kernel(const void* ei, int E, int M) {
    int e = blockIdx.x * blockDim.x + threadIdx.x;
    if (e >= E) return;
    int s, d;
    if (g_is64) {
        const long long* p = (const long long*)ei;
        s = (int)p[e];
        d = (int)p[(size_t)E + e];
    } else {
        const int* p = (const int*)ei;
        s = p[e];
        d = p[(size_t)E + e];
    }
    s = min(max(s, 0), M - 1);
    d = min(max(d, 0), M - 1);
    g_src[e] = s;
    g_dst[e] = d;
    atomicAdd(&g_deg[d], 1);
}

// single-block exclusive scan of g_deg -> g_off / g_cursor
__global__ __launch_bounds__(1024) void scan_kernel(int M, int E) {
    __shared__ int part[1024];
    const int t = threadIdx.x;
    const int chunk = (M + 1023) >> 10;
    const int lo = min(t * chunk, M);
    const int hi = min(lo + chunk, M);

    int s = 0;
    for (int i = lo; i < hi; i++) s += g_deg[i];
    part[t] = s;
    __syncthreads();
    for (int off = 1; off < 1024; off <<= 1) {
        int v = (t >= off) ? part[t - off] : 0;
        __syncthreads();
        part[t] += v;
        __syncthreads();
    }
    int run = (t > 0) ? part[t - 1] : 0;   // exclusive base
    for (int i = lo; i < hi; i++) {
        g_off[i] = run;
        g_cursor[i] = run;
        run += g_deg[i];
    }
    if (t == 0) g_off[M] = E;
}

// bucket-fill edges by dst
__global__ void fill_kernel(const float* __restrict__ ew, int E) {
    int e = blockIdx.x * blockDim.x + threadIdx.x;
    if (e >= E) return;
    int d = g_dst[e];
    int pos = atomicAdd(&g_cursor[d], 1);
    g_csr_src[pos] = g_src[e];
    g_csr_w[pos] = ew[e];
}

// ---------------------------------------------------------------------------
// GEMM1: support1 = X[M,512] @ W1[512,128]
// BM=128, BN=64, BK=16, TM=8, TN=4, 256 threads
// ---------------------------------------------------------------------------
#define G1_BM 128
#define G1_BN 64
#define G1_BK 16

__global__ __launch_bounds__(256) void gemm1_kernel(
    const float* __restrict__ A, const float* __restrict__ B, int M)
{
    __shared__ float As[G1_BK][G1_BM + 1];
    __shared__ float Bs[G1_BK][G1_BN];

    const int tid = threadIdx.x;
    const int blockRow = blockIdx.y * G1_BM;
    const int blockCol = blockIdx.x * G1_BN;

    const int tr = tid / 16;
    const int tc = tid % 16;

    float acc[8][4];
#pragma unroll
    for (int i = 0; i < 8; i++)
#pragma unroll
        for (int j = 0; j < 4; j++) acc[i][j] = 0.f;

    const int lbr = tid / 16;
    const int lbc = (tid % 16) * 4;

    for (int k0 = 0; k0 < FIN; k0 += G1_BK) {
#pragma unroll
        for (int l = 0; l < 2; l++) {
            int lin = tid + l * 256;
            int lar = lin / 4;
            int lac = (lin % 4) * 4;
            int gr = blockRow + lar;
            float4 av = make_float4(0.f, 0.f, 0.f, 0.f);
            if (gr < M)
                av = *(const float4*)(A + (size_t)gr * FIN + k0 + lac);
            As[lac + 0][lar] = av.x;
            As[lac + 1][lar] = av.y;
            As[lac + 2][lar] = av.z;
            As[lac + 3][lar] = av.w;
        }
        {
            float4 bv = *(const float4*)(B + (size_t)(k0 + lbr) * FHID + blockCol + lbc);
            *(float4*)&Bs[lbr][lbc] = bv;
        }
        __syncthreads();

#pragma unroll
        for (int kk = 0; kk < G1_BK; kk++) {
            float a[8], b[4];
#pragma unroll
            for (int i = 0; i < 8; i++) a[i] = As[kk][tr * 8 + i];
#pragma unroll
            for (int j = 0; j < 4; j++) b[j] = Bs[kk][tc * 4 + j];
#pragma unroll
            for (int i = 0; i < 8; i++)
#pragma unroll
                for (int j = 0; j < 4; j++) acc[i][j] = fmaf(a[i], b[j], acc[i][j]);
        }
        __syncthreads();
    }

#pragma unroll
    for (int i = 0; i < 8; i++) {
        int gr = blockRow + tr * 8 + i;
        if (gr < M) {
            float4 v = make_float4(acc[i][0], acc[i][1], acc[i][2], acc[i][3]);
            *(float4*)(g_support1 + (size_t)gr * FHID + blockCol + tc * 4) = v;
        }
    }
}

// ---------------------------------------------------------------------------
// Agg1 (CSR): agg1[n] = sum_{e in csr[n]} w_e * support1[src_e]
// Warp per node, one float4 (4 feats) per lane = 128 feats. No atomics.
// ---------------------------------------------------------------------------
__global__ __launch_bounds__(256) void agg1_kernel(int M)
{
    int node = (int)(((size_t)blockIdx.x * blockDim.x + threadIdx.x) >> 5);
    int lane = threadIdx.x & 31;
    if (node >= M) return;

    int beg = g_off[node];
    int end = g_off[node + 1];

    float4 acc = make_float4(0.f, 0.f, 0.f, 0.f);
    int i = beg;
    // 2-way unroll for MLP
    for (; i + 1 < end; i += 2) {
        int   s0 = g_csr_src[i],     s1 = g_csr_src[i + 1];
        float w0 = g_csr_w[i],       w1 = g_csr_w[i + 1];
        float4 v0 = ((const float4*)(g_support1 + (size_t)s0 * FHID))[lane];
        float4 v1 = ((const float4*)(g_support1 + (size_t)s1 * FHID))[lane];
        acc.x = fmaf(w0, v0.x, acc.x); acc.y = fmaf(w0, v0.y, acc.y);
        acc.z = fmaf(w0, v0.z, acc.z); acc.w = fmaf(w0, v0.w, acc.w);
        acc.x = fmaf(w1, v1.x, acc.x); acc.y = fmaf(w1, v1.y, acc.y);
        acc.z = fmaf(w1, v1.z, acc.z); acc.w = fmaf(w1, v1.w, acc.w);
    }
    if (i < end) {
        int s = g_csr_src[i];
        float w = g_csr_w[i];
        float4 v = ((const float4*)(g_support1 + (size_t)s * FHID))[lane];
        acc.x = fmaf(w, v.x, acc.x); acc.y = fmaf(w, v.y, acc.y);
        acc.z = fmaf(w, v.z, acc.z); acc.w = fmaf(w, v.w, acc.w);
    }
    ((float4*)(g_agg1 + (size_t)node * FHID))[lane] = acc;
}

// ---------------------------------------------------------------------------
// GEMM2 (fused bias+relu on the input load):
//   support2 = relu(agg1 + b1) @ W2[128,40]
// ---------------------------------------------------------------------------
__global__ __launch_bounds__(256) void gemm2_kernel(
    const float* __restrict__ W2, const float* __restrict__ b1, int M)
{
    __shared__ float Ws[FHID * FOUT];
    __shared__ float Xs[32 * FHID];

    const int tid = threadIdx.x;
    const int row0 = blockIdx.x * 32;

    for (int i = tid; i < FHID * FOUT; i += 256) Ws[i] = W2[i];

    for (int i = tid; i < 1024; i += 256) {
        int r = i >> 5;
        int c4 = (i & 31) * 4;
        int gr = row0 + r;
        float4 v = make_float4(0.f, 0.f, 0.f, 0.f);
        if (gr < M) {
            v = *(const float4*)(g_agg1 + (size_t)gr * FHID + c4);
            v.x = fmaxf(v.x + b1[c4 + 0], 0.f);
            v.y = fmaxf(v.y + b1[c4 + 1], 0.f);
            v.z = fmaxf(v.z + b1[c4 + 2], 0.f);
            v.w = fmaxf(v.w + b1[c4 + 3], 0.f);
        }
        *(float4*)&Xs[r * FHID + c4] = v;
    }
    __syncthreads();

    for (int o = tid; o < 32 * FOUT; o += 256) {
        int r = o / FOUT;
        int c = o % FOUT;
        float acc = 0.f;
        const float* xr = &Xs[r * FHID];
#pragma unroll 8
        for (int k = 0; k < FHID; k++) acc = fmaf(xr[k], Ws[k * FOUT + c], acc);
        int gr = row0 + r;
        if (gr < M) g_support2[(size_t)gr * FOUT + c] = acc;
    }
}

// ---------------------------------------------------------------------------
// Agg2 + bias + log_softmax fused (CSR): 8 threads per node, 5 feats each.
// out[n] = log_softmax( sum_e w_e * support2[src_e] + b2 )
// ---------------------------------------------------------------------------
__global__ __launch_bounds__(256) void agg2_lsm_kernel(
    const float* __restrict__ b2, float* __restrict__ out, int M)
{
    size_t gid = (size_t)blockIdx.x * blockDim.x + threadIdx.x;
    int node = (int)(gid >> 3);
    int t = (int)(gid & 7);          // 0..7, 5 feats each
    if (node >= M) return;

    int beg = g_off[node];
    int end = g_off[node + 1];

    float acc[5] = {0.f, 0.f, 0.f, 0.f, 0.f};
    for (int i = beg; i < end; i++) {
        int s = g_csr_src[i];
        float w = g_csr_w[i];
        const float* row = g_support2 + (size_t)s * FOUT + t * 5;
#pragma unroll
        for (int j = 0; j < 5; j++) acc[j] = fmaf(w, row[j], acc[j]);
    }
#pragma unroll
    for (int j = 0; j < 5; j++) acc[j] += b2[t * 5 + j];

    // max over 40 (8-lane subgroup reduction; groups are lane-aligned)
    float m = acc[0];
#pragma unroll
    for (int j = 1; j < 5; j++) m = fmaxf(m, acc[j]);
#pragma unroll
    for (int off = 1; off < 8; off <<= 1)
        m = fmaxf(m, __shfl_xor_sync(0xffffffffu, m, off));

    float ssum = 0.f;
#pragma unroll
    for (int j = 0; j < 5; j++) ssum += __expf(acc[j] - m);
#pragma unroll
    for (int off = 1; off < 8; off <<= 1)
        ssum += __shfl_xor_sync(0xffffffffu, ssum, off);

    float l = m + __logf(ssum);
    float* op = out + (size_t)node * FOUT + t * 5;
#pragma unroll
    for (int j = 0; j < 5; j++) op[j] = acc[j] - l;
}

// ---------------------------------------------------------------------------
// Launch
// ---------------------------------------------------------------------------
extern "C" void kernel_launch(void* const* d_in, const int* in_sizes, int n_in,
                              void* d_out, int out_size)
{
    const float* x   = (const float*)d_in[0];
    const void*  ei  = d_in[1];
    const float* ew  = (const float*)d_in[2];
    const float* W1  = (const float*)d_in[3];
    const float* b1  = (const float*)d_in[4];
    const float* W2  = (const float*)d_in[5];
    const float* b2  = (const float*)d_in[6];
    float* out = (float*)d_out;

    const int M = in_sizes[0] / FIN;     // 100000
    const int E = in_sizes[2];           // 3200000

    // CSR build (per replay; deterministic inputs)
    detect_kernel<<<1, 1>>>(ei, E, M);
    zero_deg_kernel<<<(M + 255) / 256, 256>>>(M);
    decode_hist_kernel<<<(E + 255) / 256, 256>>>(ei, E, M);
    scan_kernel<<<1, 1024>>>(M, E);
    fill_kernel<<<(E + 255) / 256, 256>>>(ew, E);

    // Layer 1 GEMM
    {
        dim3 grid(FHID / G1_BN, (M + G1_BM - 1) / G1_BM);
        gemm1_kernel<<<grid, 256>>>(x, W1, M);
    }

    // Layer 1 aggregation (warp per node)
    {
        size_t threads = (size_t)M * 32;
        agg1_kernel<<<(unsigned)((threads + 255) / 256), 256>>>(M);
    }

    // Layer 2 GEMM (fused bias+relu on load)
    gemm2_kernel<<<(M + 31) / 32, 256>>>(W2, b1, M);

    // Layer 2 aggregation + bias + log_softmax (8 threads per node)
    {
        size_t threads = (size_t)M * 8;
        agg2_lsm_kernel<<<(unsigned)((threads + 255) / 256), 256>>>(b2, out, M);
    }
}

// round 4
// speedup vs baseline: 1.8849x; 1.8849x over previous
#include <cuda_runtime.h>
#include <cuda_bf16.h>

// Problem constants (fixed by the dataset)
#define NNODES   100000
#define FIN      512
#define FHID     128
#define FOUT     40
#define NEDGES   3200000

#define SB 256           // scan block size
#define MAXSB 1024       // max scan blocks (ceil(NNODES/SB)=391 < 1024)

// Scratch (device globals; no runtime allocation allowed)
__device__ __align__(256) float g_support1[(size_t)NNODES * FHID];
__device__ __align__(256) float g_agg1[(size_t)NNODES * FHID];
__device__ __align__(256) float g_support2[(size_t)NNODES * FOUT];
__device__ __align__(256) int   g_src[NEDGES];
__device__ __align__(256) int   g_dst[NEDGES];
__device__ __align__(256) int   g_deg[NNODES];
__device__ __align__(256) int   g_off[NNODES + 1];
__device__ __align__(256) int   g_cursor[NNODES];
__device__ __align__(256) int   g_csr_src[NEDGES];
__device__ __align__(256) float g_csr_w[NEDGES];
__device__ __align__(256) int   g_bsum[MAXSB];
__device__ __align__(256) int   g_bbase[MAXSB];
__device__ int g_is64;

// ---------------------------------------------------------------------------
// Edge-index dtype detection (int64 vs int32), parallel: 256 thr x 16 samples
// ---------------------------------------------------------------------------
__global__ void detect_kernel(const void* ei, int E, int M) {
    const long long* p64 = (const long long*)ei;
    int step = E / 4096;
    int bad = 0;
#pragma unroll
    for (int j = 0; j < 16; j++) {
        int k = threadIdx.x * 16 + j;
        long long v = p64[(long long)k * step];
        if (v < 0 || v >= M) bad = 1;
    }
    bad = __syncthreads_or(bad);
    if (threadIdx.x == 0) g_is64 = !bad;
}

__global__ void zero_deg_kernel(int M) {
    int i = blockIdx.x * blockDim.x + threadIdx.x;
    if (i < M) g_deg[i] = 0;
}

// decode edge ids to int32 + histogram of dst degrees
__global__ void decode_hist_kernel(const void* ei, int E, int M) {
    int e = blockIdx.x * blockDim.x + threadIdx.x;
    if (e >= E) return;
    int s, d;
    if (g_is64) {
        const long long* p = (const long long*)ei;
        s = (int)p[e];
        d = (int)p[(size_t)E + e];
    } else {
        const int* p = (const int*)ei;
        s = p[e];
        d = p[(size_t)E + e];
    }
    s = min(max(s, 0), M - 1);
    d = min(max(d, 0), M - 1);
    g_src[e] = s;
    g_dst[e] = d;
    atomicAdd(&g_deg[d], 1);
}

// ---- 3-phase multi-block exclusive scan of g_deg -> g_off / g_cursor ------
__global__ void scan1_kernel(int M) {
    __shared__ int sh[SB];
    int t = threadIdx.x;
    int i = blockIdx.x * SB + t;
    sh[t] = (i < M) ? g_deg[i] : 0;
    __syncthreads();
#pragma unroll
    for (int o = SB / 2; o > 0; o >>= 1) {
        if (t < o) sh[t] += sh[t + o];
        __syncthreads();
    }
    if (t == 0) g_bsum[blockIdx.x] = sh[0];
}

__global__ __launch_bounds__(MAXSB) void scan2_kernel(int nb, int E, int M) {
    __shared__ int sh[MAXSB];
    int t = threadIdx.x;
    sh[t] = (t < nb) ? g_bsum[t] : 0;
    __syncthreads();
#pragma unroll
    for (int o = 1; o < MAXSB; o <<= 1) {
        int u = (t >= o) ? sh[t - o] : 0;
        __syncthreads();
        sh[t] += u;
        __syncthreads();
    }
    if (t < nb) g_bbase[t] = (t > 0) ? sh[t - 1] : 0;
    if (t == 0) g_off[M] = E;
}

__global__ void scan3_kernel(int M) {
    __shared__ int sh[SB];
    int t = threadIdx.x;
    int i = blockIdx.x * SB + t;
    int v = (i < M) ? g_deg[i] : 0;
    sh[t] = v;
    __syncthreads();
#pragma unroll
    for (int o = 1; o < SB; o <<= 1) {
        int u = (t >= o) ? sh[t - o] : 0;
        __syncthreads();
        sh[t] += u;
        __syncthreads();
    }
    if (i < M) {
        int excl = sh[t] - v + g_bbase[blockIdx.x];
        g_off[i] = excl;
        g_cursor[i] = excl;
    }
}

// bucket-fill edges by dst
__global__ void fill_kernel(const float* __restrict__ ew, int E) {
    int e = blockIdx.x * blockDim.x + threadIdx.x;
    if (e >= E) return;
    int d = g_dst[e];
    int pos = atomicAdd(&g_cursor[d], 1);
    g_csr_src[pos] = g_src[e];
    g_csr_w[pos] = ew[e];
}

// ---------------------------------------------------------------------------
// GEMM1: support1 = X[M,512] @ W1[512,128]
// BM=128, BN=128(=FHID), BK=16, TM=8, TN=8, 256 threads
// ---------------------------------------------------------------------------
#define G1_BM 128
#define G1_BN 128
#define G1_BK 16

__global__ __launch_bounds__(256) void gemm1_kernel(
    const float* __restrict__ A, const float* __restrict__ B, int M)
{
    __shared__ float As[G1_BK][G1_BM];   // [k][m] (transposed on store)
    __shared__ float Bs[G1_BK][G1_BN];   // [k][n]

    const int tid = threadIdx.x;
    const int blockRow = blockIdx.x * G1_BM;
    const int tr = tid / 16;       // 0..15 -> rows tr*8..tr*8+7
    const int tc = tid % 16;       // 0..15 -> cols tc*8..tc*8+7

    float acc[8][8];
#pragma unroll
    for (int i = 0; i < 8; i++)
#pragma unroll
        for (int j = 0; j < 8; j++) acc[i][j] = 0.f;

    for (int k0 = 0; k0 < FIN; k0 += G1_BK) {
        // A tile: 128 rows x 16 k = 512 float4 (each = 4 k for one row)
#pragma unroll
        for (int l = 0; l < 2; l++) {
            int lin = tid + l * 256;
            int row = lin >> 2;            // 0..127
            int kc = (lin & 3) * 4;        // 0,4,8,12
            int gr = blockRow + row;
            float4 av = make_float4(0.f, 0.f, 0.f, 0.f);
            if (gr < M)
                av = *(const float4*)(A + (size_t)gr * FIN + k0 + kc);
            As[kc + 0][row] = av.x;
            As[kc + 1][row] = av.y;
            As[kc + 2][row] = av.z;
            As[kc + 3][row] = av.w;
        }
        // B tile: 16 k x 128 n = 512 float4
#pragma unroll
        for (int l = 0; l < 2; l++) {
            int lin = tid + l * 256;
            int kr = lin >> 5;             // 0..15
            int nc = (lin & 31) * 4;       // 0..124
            *(float4*)&Bs[kr][nc] = *(const float4*)(B + (size_t)(k0 + kr) * FHID + nc);
        }
        __syncthreads();

#pragma unroll
        for (int kk = 0; kk < G1_BK; kk++) {
            float a[8], b[8];
            *(float4*)&a[0] = *(const float4*)&As[kk][tr * 8];
            *(float4*)&a[4] = *(const float4*)&As[kk][tr * 8 + 4];
            *(float4*)&b[0] = *(const float4*)&Bs[kk][tc * 8];
            *(float4*)&b[4] = *(const float4*)&Bs[kk][tc * 8 + 4];
#pragma unroll
            for (int i = 0; i < 8; i++)
#pragma unroll
                for (int j = 0; j < 8; j++) acc[i][j] = fmaf(a[i], b[j], acc[i][j]);
        }
        __syncthreads();
    }

#pragma unroll
    for (int i = 0; i < 8; i++) {
        int gr = blockRow + tr * 8 + i;
        if (gr < M) {
            float* op = g_support1 + (size_t)gr * FHID + tc * 8;
            *(float4*)op       = make_float4(acc[i][0], acc[i][1], acc[i][2], acc[i][3]);
            *(float4*)(op + 4) = make_float4(acc[i][4], acc[i][5], acc[i][6], acc[i][7]);
        }
    }
}

// ---------------------------------------------------------------------------
// Agg1 (CSR): agg1[n] = sum_{e in csr[n]} w_e * support1[src_e]
// Warp per node, one float4 (4 feats) per lane = 128 feats. No atomics.
// ---------------------------------------------------------------------------
__global__ __launch_bounds__(256) void agg1_kernel(int M)
{
    int node = (int)(((size_t)blockIdx.x * blockDim.x + threadIdx.x) >> 5);
    int lane = threadIdx.x & 31;
    if (node >= M) return;

    int beg = g_off[node];
    int end = g_off[node + 1];

    float4 acc = make_float4(0.f, 0.f, 0.f, 0.f);
    int i = beg;
    for (; i + 1 < end; i += 2) {
        int   s0 = g_csr_src[i],     s1 = g_csr_src[i + 1];
        float w0 = g_csr_w[i],       w1 = g_csr_w[i + 1];
        float4 v0 = ((const float4*)(g_support1 + (size_t)s0 * FHID))[lane];
        float4 v1 = ((const float4*)(g_support1 + (size_t)s1 * FHID))[lane];
        acc.x = fmaf(w0, v0.x, acc.x); acc.y = fmaf(w0, v0.y, acc.y);
        acc.z = fmaf(w0, v0.z, acc.z); acc.w = fmaf(w0, v0.w, acc.w);
        acc.x = fmaf(w1, v1.x, acc.x); acc.y = fmaf(w1, v1.y, acc.y);
        acc.z = fmaf(w1, v1.z, acc.z); acc.w = fmaf(w1, v1.w, acc.w);
    }
    if (i < end) {
        int s = g_csr_src[i];
        float w = g_csr_w[i];
        float4 v = ((const float4*)(g_support1 + (size_t)s * FHID))[lane];
        acc.x = fmaf(w, v.x, acc.x); acc.y = fmaf(w, v.y, acc.y);
        acc.z = fmaf(w, v.z, acc.z); acc.w = fmaf(w, v.w, acc.w);
    }
    ((float4*)(g_agg1 + (size_t)node * FHID))[lane] = acc;
}

// ---------------------------------------------------------------------------
// GEMM2 (fused bias+relu on input load): support2 = relu(agg1+b1) @ W2[128,40]
// ---------------------------------------------------------------------------
__global__ __launch_bounds__(256) void gemm2_kernel(
    const float* __restrict__ W2, const float* __restrict__ b1, int M)
{
    __shared__ float Ws[FHID * FOUT];
    __shared__ float Xs[32 * FHID];

    const int tid = threadIdx.x;
    const int row0 = blockIdx.x * 32;

    for (int i = tid; i < FHID * FOUT; i += 256) Ws[i] = W2[i];

    for (int i = tid; i < 1024; i += 256) {
        int r = i >> 5;
        int c4 = (i & 31) * 4;
        int gr = row0 + r;
        float4 v = make_float4(0.f, 0.f, 0.f, 0.f);
        if (gr < M) {
            v = *(const float4*)(g_agg1 + (size_t)gr * FHID + c4);
            v.x = fmaxf(v.x + b1[c4 + 0], 0.f);
            v.y = fmaxf(v.y + b1[c4 + 1], 0.f);
            v.z = fmaxf(v.z + b1[c4 + 2], 0.f);
            v.w = fmaxf(v.w + b1[c4 + 3], 0.f);
        }
        *(float4*)&Xs[r * FHID + c4] = v;
    }
    __syncthreads();

    for (int o = tid; o < 32 * FOUT; o += 256) {
        int r = o / FOUT;
        int c = o % FOUT;
        float acc = 0.f;
        const float* xr = &Xs[r * FHID];
#pragma unroll 8
        for (int k = 0; k < FHID; k++) acc = fmaf(xr[k], Ws[k * FOUT + c], acc);
        int gr = row0 + r;
        if (gr < M) g_support2[(size_t)gr * FOUT + c] = acc;
    }
}

// ---------------------------------------------------------------------------
// Agg2 + bias + log_softmax fused (CSR): 8 threads per node, 5 feats each.
// ---------------------------------------------------------------------------
__global__ __launch_bounds__(256) void agg2_lsm_kernel(
    const float* __restrict__ b2, float* __restrict__ out, int M)
{
    size_t gid = (size_t)blockIdx.x * blockDim.x + threadIdx.x;
    int node = (int)(gid >> 3);
    int t = (int)(gid & 7);
    if (node >= M) return;

    int beg = g_off[node];
    int end = g_off[node + 1];

    float acc[5] = {0.f, 0.f, 0.f, 0.f, 0.f};
    for (int i = beg; i < end; i++) {
        int s = g_csr_src[i];
        float w = g_csr_w[i];
        const float* row = g_support2 + (size_t)s * FOUT + t * 5;
#pragma unroll
        for (int j = 0; j < 5; j++) acc[j] = fmaf(w, row[j], acc[j]);
    }
#pragma unroll
    for (int j = 0; j < 5; j++) acc[j] += b2[t * 5 + j];

    float m = acc[0];
#pragma unroll
    for (int j = 1; j < 5; j++) m = fmaxf(m, acc[j]);
#pragma unroll
    for (int off = 1; off < 8; off <<= 1)
        m = fmaxf(m, __shfl_xor_sync(0xffffffffu, m, off));

    float ssum = 0.f;
#pragma unroll
    for (int j = 0; j < 5; j++) ssum += __expf(acc[j] - m);
#pragma unroll
    for (int off = 1; off < 8; off <<= 1)
        ssum += __shfl_xor_sync(0xffffffffu, ssum, off);

    float l = m + __logf(ssum);
    float* op = out + (size_t)node * FOUT + t * 5;
#pragma unroll
    for (int j = 0; j < 5; j++) op[j] = acc[j] - l;
}

// ---------------------------------------------------------------------------
// Launch
// ---------------------------------------------------------------------------
extern "C" void kernel_launch(void* const* d_in, const int* in_sizes, int n_in,
                              void* d_out, int out_size)
{
    const float* x   = (const float*)d_in[0];
    const void*  ei  = d_in[1];
    const float* ew  = (const float*)d_in[2];
    const float* W1  = (const float*)d_in[3];
    const float* b1  = (const float*)d_in[4];
    const float* W2  = (const float*)d_in[5];
    const float* b2  = (const float*)d_in[6];
    float* out = (float*)d_out;

    const int M = in_sizes[0] / FIN;     // 100000
    const int E = in_sizes[2];           // 3200000
    const int nb = (M + SB - 1) / SB;    // scan blocks (391)

    // CSR build (parallel; per replay)
    detect_kernel<<<1, 256>>>(ei, E, M);
    zero_deg_kernel<<<(M + 255) / 256, 256>>>(M);
    decode_hist_kernel<<<(E + 255) / 256, 256>>>(ei, E, M);
    scan1_kernel<<<nb, SB>>>(M);
    scan2_kernel<<<1, MAXSB>>>(nb, E, M);
    scan3_kernel<<<nb, SB>>>(M);
    fill_kernel<<<(E + 255) / 256, 256>>>(ew, E);

    // Layer 1 GEMM (BNx1 grid: FHID == BN)
    gemm1_kernel<<<(M + G1_BM - 1) / G1_BM, 256>>>(x, W1, M);

    // Layer 1 aggregation (warp per node)
    {
        size_t threads = (size_t)M * 32;
        agg1_kernel<<<(unsigned)((threads + 255) / 256), 256>>>(M);
    }

    // Layer 2 GEMM (fused bias+relu on load)
    gemm2_kernel<<<(M + 31) / 32, 256>>>(W2, b1, M);

    // Layer 2 aggregation + bias + log_softmax (8 threads per node)
    {
        size_t threads = (size_t)M * 8;
        agg2_lsm_kernel<<<(unsigned)((threads + 255) / 256), 256>>>(b2, out, M);
    }
}